// round 2
// baseline (speedup 1.0000x reference)
#include <cuda_runtime.h>
#include <cuda_bf16.h>

// Problem constants: N=64, C=4, LPC=8, KPL=4, D=4096
// BLOCK = 128, P = 384, G = LPC*KPL = 32 gaussians per (n,c) pair.
#define NN      64
#define CC      4
#define DD      4096
#define G       32
#define PP      384
#define THREADS 256
#define VEC     4
// elements per block = 1024; total blocks = 256*4 = 1024

__global__ __launch_bounds__(THREADS)
void GaussianSuperposition_kernel(const float* __restrict__ x,
                                  const float* __restrict__ net,
                                  const int*   __restrict__ amp_idx,
                                  const int*   __restrict__ mu_idx,
                                  const int*   __restrict__ sigma_idx,
                                  float*       __restrict__ out) {
    __shared__ float s_b[G];    // -0.5/sigma^2
    __shared__ float s_p[G];    // -2*b*mu
    __shared__ float s_q[G];    //  b*mu*mu
    __shared__ float s_a[G];    //  amp

    const int blk  = blockIdx.x;        // 0..1023
    const int nc   = blk >> 2;          // 0..255  (n*C + c)
    const int tile = blk & 3;           // 0..3
    const int n    = nc >> 2;
    const int c    = nc & 3;
    const int t    = threadIdx.x;

    if (t < G) {
        const int base = c * G + t;     // flat index into (C, LPC, KPL) idx arrays
        const float* row = net + n * PP;
        const float amp = row[amp_idx[base]];
        const float mu  = row[mu_idx[base]];
        const float sg  = row[sigma_idx[base]];
        // exponent(x) = -0.5*(x-mu)^2/sg^2 = (b*x + p)*x + q
        const float b = -0.5f / (sg * sg);
        s_b[t] = b;
        s_p[t] = -2.0f * b * mu;
        s_q[t] = b * mu * mu;
        s_a[t] = amp;
    }
    __syncthreads();

    const int off = nc * DD + tile * (THREADS * VEC) + t * VEC;

    const float4 xv = *reinterpret_cast<const float4*>(x + off);

    float a0 = 0.0f, a1 = 0.0f, a2 = 0.0f, a3 = 0.0f;

#pragma unroll
    for (int j = 0; j < G; ++j) {
        const float b   = s_b[j];
        const float p   = s_p[j];
        const float q   = s_q[j];
        const float amp = s_a[j];

        const float e0 = fmaf(fmaf(b, xv.x, p), xv.x, q);
        const float e1 = fmaf(fmaf(b, xv.y, p), xv.y, q);
        const float e2 = fmaf(fmaf(b, xv.z, p), xv.z, q);
        const float e3 = fmaf(fmaf(b, xv.w, p), xv.w, q);

        a0 = fmaf(amp, __expf(e0), a0);
        a1 = fmaf(amp, __expf(e1), a1);
        a2 = fmaf(amp, __expf(e2), a2);
        a3 = fmaf(amp, __expf(e3), a3);
    }

    float4 ov;
    ov.x = a0; ov.y = a1; ov.z = a2; ov.w = a3;
    *reinterpret_cast<float4*>(out + off) = ov;
}

extern "C" void kernel_launch(void* const* d_in, const int* in_sizes, int n_in,
                              void* d_out, int out_size) {
    // Defensive input binding: identify tensors by element count instead of
    // trusting position. x: 1,048,576 f32; net: 24,576 f32; idx arrays: 128 i32
    // each, taken in order of appearance (amp, mu, sigma).
    const float* x   = nullptr;
    const float* net = nullptr;
    const int*   idx[3] = {nullptr, nullptr, nullptr};
    int nidx = 0;
    for (int i = 0; i < n_in; ++i) {
        const int sz = in_sizes[i];
        if (sz == NN * CC * DD)      x   = (const float*)d_in[i];
        else if (sz == NN * PP)      net = (const float*)d_in[i];
        else if (sz == CC * G && nidx < 3) idx[nidx++] = (const int*)d_in[i];
    }
    if (!x || !net || nidx != 3) return;  // shape mismatch: do nothing (fails loudly in capture)

    float* out = (float*)d_out;
    GaussianSuperposition_kernel<<<NN * CC * 4, THREADS>>>(x, net, idx[0], idx[1], idx[2], out);
}

// round 3
// speedup vs baseline: 1.3761x; 1.3761x over previous
#include <cuda_runtime.h>
#include <cuda_bf16.h>

// Problem constants: N=64, C=4, LPC=8, KPL=4, D=4096
// BLOCK = 128, P = 384, G = LPC*KPL = 32 gaussians per (n,c) pair.
#define NN      64
#define CC      4
#define DD      4096
#define G       32
#define PP      384
#define THREADS 128
#define VEC     8
// elements per block = THREADS*VEC = 1024 ; grid = 256 nc-pairs * 4 tiles = 1024

__device__ __forceinline__ float ex2_approx(float v) {
    float r;
    asm("ex2.approx.ftz.f32 %0, %1;" : "=f"(r) : "f"(v));
    return r;
}

__global__ __launch_bounds__(THREADS)
void GaussianSuperposition_kernel(const float* __restrict__ x,
                                  const float* __restrict__ net,
                                  const int*   __restrict__ amp_idx,
                                  const int*   __restrict__ mu_idx,
                                  const int*   __restrict__ sigma_idx,
                                  float*       __restrict__ out) {
    // Packed per-gaussian coefficients: (b, p, q, amp) with log2(e) folded in:
    // exponent2(x) = (b*x + p)*x + q  such that 2^exponent2 == exp(-0.5*(x-mu)^2/sg^2)
    __shared__ float4 s_c[G];

    const int blk  = blockIdx.x;        // 0..1023
    const int nc   = blk >> 2;          // 0..255  (n*C + c)
    const int tile = blk & 3;           // 0..3
    const int n    = nc >> 2;
    const int c    = nc & 3;
    const int t    = threadIdx.x;

    if (t < G) {
        const int base = c * G + t;
        const float* row = net + n * PP;
        const float amp = row[amp_idx[base]];
        const float mu  = row[mu_idx[base]];
        const float sg  = row[sigma_idx[base]];
        // b = -0.5*log2(e)/sg^2 ; p = -2*b*mu ; q = b*mu*mu
        const float b = -0.72134752044448170f / (sg * sg);
        float4 cv;
        cv.x = b;
        cv.y = -2.0f * b * mu;
        cv.z = b * mu * mu;
        cv.w = amp;
        s_c[t] = cv;
    }
    __syncthreads();

    const int base = nc * DD + tile * (THREADS * VEC);
    const int off0 = base + t * 4;          // first float4 (coalesced over warp)
    const int off1 = off0 + THREADS * 4;    // second float4, 512 elements later

    const float4 xa = *reinterpret_cast<const float4*>(x + off0);
    const float4 xb = *reinterpret_cast<const float4*>(x + off1);

    float a0 = 0.f, a1 = 0.f, a2 = 0.f, a3 = 0.f;
    float a4 = 0.f, a5 = 0.f, a6 = 0.f, a7 = 0.f;

#pragma unroll
    for (int j = 0; j < G; ++j) {
        const float4 cv = s_c[j];
        const float b = cv.x, p = cv.y, q = cv.z, amp = cv.w;

        const float e0 = fmaf(fmaf(b, xa.x, p), xa.x, q);
        const float e1 = fmaf(fmaf(b, xa.y, p), xa.y, q);
        const float e2 = fmaf(fmaf(b, xa.z, p), xa.z, q);
        const float e3 = fmaf(fmaf(b, xa.w, p), xa.w, q);
        const float e4 = fmaf(fmaf(b, xb.x, p), xb.x, q);
        const float e5 = fmaf(fmaf(b, xb.y, p), xb.y, q);
        const float e6 = fmaf(fmaf(b, xb.z, p), xb.z, q);
        const float e7 = fmaf(fmaf(b, xb.w, p), xb.w, q);

        a0 = fmaf(amp, ex2_approx(e0), a0);
        a1 = fmaf(amp, ex2_approx(e1), a1);
        a2 = fmaf(amp, ex2_approx(e2), a2);
        a3 = fmaf(amp, ex2_approx(e3), a3);
        a4 = fmaf(amp, ex2_approx(e4), a4);
        a5 = fmaf(amp, ex2_approx(e5), a5);
        a6 = fmaf(amp, ex2_approx(e6), a6);
        a7 = fmaf(amp, ex2_approx(e7), a7);
    }

    float4 o0; o0.x = a0; o0.y = a1; o0.z = a2; o0.w = a3;
    float4 o1; o1.x = a4; o1.y = a5; o1.z = a6; o1.w = a7;
    *reinterpret_cast<float4*>(out + off0) = o0;
    *reinterpret_cast<float4*>(out + off1) = o1;
}

extern "C" void kernel_launch(void* const* d_in, const int* in_sizes, int n_in,
                              void* d_out, int out_size) {
    // Defensive input binding by element count (x: 1,048,576 f32; net: 24,576 f32;
    // three 128-element i32 index arrays in order: amp, mu, sigma).
    const float* x   = nullptr;
    const float* net = nullptr;
    const int*   idx[3] = {nullptr, nullptr, nullptr};
    int nidx = 0;
    for (int i = 0; i < n_in; ++i) {
        const int sz = in_sizes[i];
        if (sz == NN * CC * DD)      x   = (const float*)d_in[i];
        else if (sz == NN * PP)      net = (const float*)d_in[i];
        else if (sz == CC * G && nidx < 3) idx[nidx++] = (const int*)d_in[i];
    }
    if (!x || !net || nidx != 3) return;

    float* out = (float*)d_out;
    GaussianSuperposition_kernel<<<NN * CC * 4, THREADS>>>(x, net, idx[0], idx[1], idx[2], out);
}

// round 4
// speedup vs baseline: 1.4132x; 1.0269x over previous
#include <cuda_runtime.h>
#include <cuda_bf16.h>

// Problem constants: N=64, C=4, LPC=8, KPL=4, D=4096
// BLOCK = 128, P = 384, G = LPC*KPL = 32 gaussians per (n,c) pair.
#define NN      64
#define CC      4
#define DD      4096
#define G       32
#define PP      384
#define THREADS 128
#define VEC     8
// elements per block = THREADS*VEC = 1024 ; grid = 256 nc-pairs * 4 tiles = 1024

__device__ __forceinline__ float ex2_approx(float v) {
    float r;
    asm("ex2.approx.ftz.f32 %0, %1;" : "=f"(r) : "f"(v));
    return r;
}
__device__ __forceinline__ float lg2_approx(float v) {
    float r;
    asm("lg2.approx.ftz.f32 %0, %1;" : "=f"(r) : "f"(v));
    return r;
}

__global__ __launch_bounds__(THREADS)
void GaussianSuperposition_kernel(const float* __restrict__ x,
                                  const float* __restrict__ net,
                                  const int*   __restrict__ amp_idx,
                                  const int*   __restrict__ mu_idx,
                                  const int*   __restrict__ sigma_idx,
                                  float*       __restrict__ out) {
    // Packed per-gaussian coefficients (b, p, q) with log2(e) AND log2(amp) folded:
    //   amp * exp(-0.5*(x-mu)^2/sg^2) == 2^((b*x + p)*x + q)
    __shared__ float4 s_c[G];

    const int blk  = blockIdx.x;        // 0..1023
    const int nc   = blk >> 2;          // 0..255  (n*C + c)
    const int tile = blk & 3;           // 0..3
    const int n    = nc >> 2;
    const int c    = nc & 3;
    const int t    = threadIdx.x;

    // Issue the x loads FIRST so their DRAM latency overlaps the coefficient
    // gather + __syncthreads below.
    const int base = nc * DD + tile * (THREADS * VEC);
    const int off0 = base + t * 4;          // first float4 (coalesced over warp)
    const int off1 = off0 + THREADS * 4;    // second float4, 512 elements later
    const float4 xa = *reinterpret_cast<const float4*>(x + off0);
    const float4 xb = *reinterpret_cast<const float4*>(x + off1);

    if (t < G) {
        const int gi = c * G + t;
        const float* row = net + n * PP;
        const float amp = row[amp_idx[gi]];
        const float mu  = row[mu_idx[gi]];
        const float sg  = row[sigma_idx[gi]];
        // b = -0.5*log2(e)/sg^2 ; p = -2*b*mu ; q = b*mu^2 + log2(amp)
        const float b = -0.72134752044448170f / (sg * sg);
        float4 cv;
        cv.x = b;
        cv.y = -2.0f * b * mu;
        cv.z = fmaf(b * mu, mu, lg2_approx(amp));
        cv.w = 0.0f;
        s_c[t] = cv;
    }
    __syncthreads();

    float a0 = 0.f, a1 = 0.f, a2 = 0.f, a3 = 0.f;
    float a4 = 0.f, a5 = 0.f, a6 = 0.f, a7 = 0.f;

    // Double-buffered coefficient prefetch: the LDS for iteration j+1 is in
    // flight while iteration j's FFMA/EX2 chain executes, so no EX2 group has
    // an LDS-latency bubble in front of it.
    float4 cv = s_c[0];

#pragma unroll
    for (int j = 0; j < G; ++j) {
        const float b = cv.x, p = cv.y, q = cv.z;
        if (j + 1 < G) cv = s_c[j + 1];

        const float e0 = fmaf(fmaf(b, xa.x, p), xa.x, q);
        const float e1 = fmaf(fmaf(b, xa.y, p), xa.y, q);
        const float e2 = fmaf(fmaf(b, xa.z, p), xa.z, q);
        const float e3 = fmaf(fmaf(b, xa.w, p), xa.w, q);
        const float e4 = fmaf(fmaf(b, xb.x, p), xb.x, q);
        const float e5 = fmaf(fmaf(b, xb.y, p), xb.y, q);
        const float e6 = fmaf(fmaf(b, xb.z, p), xb.z, q);
        const float e7 = fmaf(fmaf(b, xb.w, p), xb.w, q);

        a0 += ex2_approx(e0);
        a1 += ex2_approx(e1);
        a2 += ex2_approx(e2);
        a3 += ex2_approx(e3);
        a4 += ex2_approx(e4);
        a5 += ex2_approx(e5);
        a6 += ex2_approx(e6);
        a7 += ex2_approx(e7);
    }

    float4 o0; o0.x = a0; o0.y = a1; o0.z = a2; o0.w = a3;
    float4 o1; o1.x = a4; o1.y = a5; o1.z = a6; o1.w = a7;
    *reinterpret_cast<float4*>(out + off0) = o0;
    *reinterpret_cast<float4*>(out + off1) = o1;
}

extern "C" void kernel_launch(void* const* d_in, const int* in_sizes, int n_in,
                              void* d_out, int out_size) {
    // Defensive input binding by element count (x: 1,048,576 f32; net: 24,576 f32;
    // three 128-element i32 index arrays in order: amp, mu, sigma).
    const float* x   = nullptr;
    const float* net = nullptr;
    const int*   idx[3] = {nullptr, nullptr, nullptr};
    int nidx = 0;
    for (int i = 0; i < n_in; ++i) {
        const int sz = in_sizes[i];
        if (sz == NN * CC * DD)      x   = (const float*)d_in[i];
        else if (sz == NN * PP)      net = (const float*)d_in[i];
        else if (sz == CC * G && nidx < 3) idx[nidx++] = (const int*)d_in[i];
    }
    if (!x || !net || nidx != 3) return;

    float* out = (float*)d_out;
    GaussianSuperposition_kernel<<<NN * CC * 4, THREADS>>>(x, net, idx[0], idx[1], idx[2], out);
}